// round 15
// baseline (speedup 1.0000x reference)
#include <cuda_runtime.h>
#include <math.h>

#define B 128
#define C 1024
#define DIN 1024
#define TWO_D 2048
#define NUM_CLASSES 10
#define ALPHA 1e-3f
#define GAMMA 1e-2f

#define BM 64
#define BN 256
#define BK 32
#define BK2 (BK / 2)              // 16 packed k-pairs
#define KSPLIT 16
#define KSLICE (TWO_D / KSPLIT)   // 128  (aligned: each slice is in one half)
#define NT (KSLICE / BK)          // 4 tiles

// packed smem layout: [k2][row*2 + parity]
#define SA2_STRIDE (2 * BM + 4)           // 132 floats
#define SB2_STRIDE (2 * BN + 4)           // 516 floats
#define SA2_BUF (BK2 * SA2_STRIDE)        // 2112 floats
#define SB2_BUF (BK2 * SB2_STRIDE)        // 8256 floats
#define SMEM_FLOATS (2 * SA2_BUF + 2 * SB2_BUF)
#define SMEM_BYTES (SMEM_FLOATS * 4)      // 82944 B

typedef unsigned long long ull;

__device__ __forceinline__ ull pk2(float lo, float hi) {
    ull r; asm("mov.b64 %0, {%1, %2};" : "=l"(r) : "f"(lo), "f"(hi)); return r;
}

// two scalar mins (alu pipe) + packed f32x2 accumulate (fma pipe).
// lo/hi are fresh temps so ptxas can allocate them as an aligned pair and
// elide the mov.b64.
__device__ __forceinline__ void min2_acc(ull& acc, float ae, float be,
                                         float ao, float bo) {
    asm("{\n\t"
        ".reg .f32 lo, hi;\n\t"
        ".reg .b64 m;\n\t"
        "min.f32 lo, %1, %2;\n\t"
        "min.f32 hi, %3, %4;\n\t"
        "mov.b64 m, {lo, hi};\n\t"
        "add.rn.f32x2 %0, %0, m;\n\t"
        "}" : "+l"(acc) : "f"(ae), "f"(be), "f"(ao), "f"(bo));
}

// Scratch (static device globals; no dynamic allocation)
__device__ float g_pmin[B];
__device__ float g_pmax[B];
__device__ float g_sum[C];         // rowsum(T) via REDG
__device__ float g_choice[B][C];   // numerator via REDG

// ---------------------------------------------------------------------------
// K1 (128 CTAs x 256): row b: zero g_choice row + minmax partial of x row.
// CTA 0 additionally zeroes g_sum.
// ---------------------------------------------------------------------------
__global__ void k_prep(const float* __restrict__ x) {
    int b = blockIdx.x;
    int t = threadIdx.x;  // 256

    ((float4*)&g_choice[b][0])[t] = make_float4(0.f, 0.f, 0.f, 0.f);
    if (b == 0)
        ((float4*)g_sum)[t] = make_float4(0.f, 0.f, 0.f, 0.f);

    float4 v = ((const float4*)(x + (size_t)b * DIN))[t];
    float mn = fminf(fminf(v.x, v.y), fminf(v.z, v.w));
    float mx = fmaxf(fmaxf(v.x, v.y), fmaxf(v.z, v.w));
    #pragma unroll
    for (int o = 16; o > 0; o >>= 1) {
        mn = fminf(mn, __shfl_xor_sync(0xffffffffu, mn, o));
        mx = fmaxf(mx, __shfl_xor_sync(0xffffffffu, mx, o));
    }
    __shared__ float smn[8], smx[8];
    if ((t & 31) == 0) { smn[t >> 5] = mn; smx[t >> 5] = mx; }
    __syncthreads();
    if (t == 0) {
        #pragma unroll
        for (int w = 1; w < 8; w++) { mn = fminf(mn, smn[w]); mx = fmaxf(mx, smx[w]); }
        g_pmin[b] = mn;
        g_pmax[b] = mx;
    }
}

// ---------------------------------------------------------------------------
// K2: min-sum "GEMM", packed accumulate over k-parity. BM=64, BN=256, BK=32,
// 1024 threads, TM=TN=4. grid = (4,2,16) = 128 CTAs = one wave.
// A built on the fly from x (normalize + optional complement).
// Double-buffered dynamic smem; REDG into g_choice / g_sum.
// ---------------------------------------------------------------------------
__global__ void __launch_bounds__(1024) k_choice(const float* __restrict__ x,
                                                 const float* __restrict__ T) {
    extern __shared__ float sm[];
    float* sA = sm;                  // [2][BK2][SA2_STRIDE]
    float* sB = sm + 2 * SA2_BUF;    // [2][BK2][SB2_STRIDE]

    int tid = threadIdx.x;
    int tx = tid & 63;       // n-group -> n0 = tx*4 (BN=256)
    int ty = tid >> 6;       // m-group -> m0 = ty*4 (BM=64)
    int mbase = blockIdx.y * BM;
    int nbase = blockIdx.x * BN;
    int k0 = blockIdx.z * KSLICE;
    bool comp = (k0 >= DIN);
    int xcol = comp ? (k0 - DIN) : k0;
    bool sumDuty = (blockIdx.y == 0);

    // inline global minmax reduce (128 partials -> mnv, sc)
    __shared__ float smn[4], smx[4];
    if (tid < 128) {
        float mn = g_pmin[tid];
        float mx = g_pmax[tid];
        #pragma unroll
        for (int o = 16; o > 0; o >>= 1) {
            mn = fminf(mn, __shfl_xor_sync(0xffffffffu, mn, o));
            mx = fmaxf(mx, __shfl_xor_sync(0xffffffffu, mx, o));
        }
        if ((tid & 31) == 0) { smn[tid >> 5] = mn; smx[tid >> 5] = mx; }
    }
    __syncthreads();
    float mnv = fminf(fminf(smn[0], smn[1]), fminf(smn[2], smn[3]));
    float mxv = fmaxf(fmaxf(smx[0], smx[1]), fmaxf(smx[2], smx[3]));
    float sc = 1.0f / (mxv - mnv + 1e-10f);

    bool hasA = tid < 512;
    int ra = tid >> 3;       // A rows 0..63 (tid<512), B rows 0..127
    int kv = tid & 7;        // float4 index within BK

    const float4* pA  = (const float4*)&x[(size_t)(mbase + (hasA ? ra : 0)) * DIN + xcol + kv * 4];
    const float4* pB0 = (const float4*)&T[(size_t)(nbase + ra) * TWO_D + k0 + kv * 4];
    const float4* pB1 = (const float4*)&T[(size_t)(nbase + ra + 128) * TWO_D + k0 + kv * 4];

    ull acc2[4][4];   // packed (k-even, k-odd) accumulators
    #pragma unroll
    for (int i = 0; i < 4; i++)
        #pragma unroll
        for (int j = 0; j < 4; j++) acc2[i][j] = 0ull;

    float tsum0 = 0.0f, tsum1 = 0.0f;

    #define XFORM(v) do { \
        v.x = (v.x - mnv) * sc; v.y = (v.y - mnv) * sc; \
        v.z = (v.z - mnv) * sc; v.w = (v.w - mnv) * sc; \
        if (comp) { v.x = 1.0f - v.x; v.y = 1.0f - v.y; \
                    v.z = 1.0f - v.z; v.w = 1.0f - v.w; } \
    } while (0)

    // store a float4 (4 consecutive k, one row) into packed pair layout
    #define STORE_A(base, v) do { \
        *(ull*)((base) + (kv * 2) * SA2_STRIDE + ra * 2) = pk2(v.x, v.y); \
        *(ull*)((base) + (kv * 2 + 1) * SA2_STRIDE + ra * 2) = pk2(v.z, v.w); \
    } while (0)
    #define STORE_B(base, v, row) do { \
        *(ull*)((base) + (kv * 2) * SB2_STRIDE + (row) * 2) = pk2(v.x, v.y); \
        *(ull*)((base) + (kv * 2 + 1) * SB2_STRIDE + (row) * 2) = pk2(v.z, v.w); \
    } while (0)

    // prefetch + store tile 0 into buffer 0
    float4 va = make_float4(0.f, 0.f, 0.f, 0.f);
    if (hasA) va = pA[0];
    float4 vb0 = pB0[0], vb1 = pB1[0];
    tsum0 += (vb0.x + vb0.y) + (vb0.z + vb0.w);
    tsum1 += (vb1.x + vb1.y) + (vb1.z + vb1.w);
    {
        if (hasA) { XFORM(va); STORE_A(sA, va); }
        STORE_B(sB, vb0, ra);
        STORE_B(sB, vb1, ra + 128);
    }
    __syncthreads();

    int buf = 0;
    for (int tt = 0; tt < NT; tt++) {
        if (tt + 1 < NT) {   // prefetch next tile (overlaps compute below)
            int o = (tt + 1) * (BK / 4);
            if (hasA) va = pA[o];
            vb0 = pB0[o]; vb1 = pB1[o];
            tsum0 += (vb0.x + vb0.y) + (vb0.z + vb0.w);
            tsum1 += (vb1.x + vb1.y) + (vb1.z + vb1.w);
        }
        const float* cA = sA + buf * SA2_BUF + ty * 8;
        const float* cB = sB + buf * SB2_BUF + tx * 8;
        #pragma unroll
        for (int k2 = 0; k2 < BK2; k2++) {
            // float4 = [row_r even, row_r odd, row_r+1 even, row_r+1 odd]
            float4 a0 = *(const float4*)(cA + k2 * SA2_STRIDE);
            float4 a1 = *(const float4*)(cA + k2 * SA2_STRIDE + 4);
            float4 b0 = *(const float4*)(cB + k2 * SB2_STRIDE);
            float4 b1 = *(const float4*)(cB + k2 * SB2_STRIDE + 4);
            float ae[4] = {a0.x, a0.z, a1.x, a1.z};
            float ao[4] = {a0.y, a0.w, a1.y, a1.w};
            float be[4] = {b0.x, b0.z, b1.x, b1.z};
            float bo[4] = {b0.y, b0.w, b1.y, b1.w};
            #pragma unroll
            for (int i = 0; i < 4; i++)
                #pragma unroll
                for (int j = 0; j < 4; j++)
                    min2_acc(acc2[i][j], ae[i], be[j], ao[i], bo[j]);
        }
        if (tt + 1 < NT) {
            int nb = buf ^ 1;
            float* dA = sA + nb * SA2_BUF;
            float* dB = sB + nb * SB2_BUF;
            if (hasA) { XFORM(va); STORE_A(dA, va); }
            STORE_B(dB, vb0, ra);
            STORE_B(dB, vb1, ra + 128);
            __syncthreads();
            buf = nb;
        }
    }
    #undef XFORM
    #undef STORE_A
    #undef STORE_B

    if (sumDuty) {
        atomicAdd(&g_sum[nbase + ra], tsum0);
        atomicAdd(&g_sum[nbase + ra + 128], tsum1);
    }

    // unpack (lo+hi) and REDG into g_choice
    int b0 = mbase + ty * 4;
    int c0 = nbase + tx * 4;
    #pragma unroll
    for (int i = 0; i < 4; i++)
        #pragma unroll
        for (int j = 0; j < 4; j++) {
            float lo, hi;
            asm("mov.b64 {%0, %1}, %2;" : "=f"(lo), "=f"(hi) : "l"(acc2[i][j]));
            atomicAdd(&g_choice[b0 + i][c0 + j], lo + hi);
        }
}

// ---------------------------------------------------------------------------
// K3: per batch row, 256 threads, 4 categories/thread (float4/int4 loads):
// den = alpha + g_sum[c] + gamma*counts[c]; divide, masked argmax
// (first-index tie), per-label sums via per-warp smem rows, one-hot output.
// committed is int32.
// ---------------------------------------------------------------------------
__global__ void __launch_bounds__(256) k_final(const int* __restrict__ committed,
                                               const int* __restrict__ labels,
                                               const int* __restrict__ counts,
                                               float* __restrict__ out) {
    int b = blockIdx.x;
    int t = threadIdx.x;        // 0..255, cats c = 4t..4t+3
    int lane = t & 31;
    int wid = t >> 5;
    __shared__ float sbins[8][NUM_CLASSES];
    __shared__ float bins[NUM_CLASSES];
    __shared__ float wval[8];
    __shared__ int widx[8];

    if (lane < NUM_CLASSES) sbins[wid][lane] = 0.0f;
    __syncthreads();

    float4 ch = ((const float4*)&g_choice[b][0])[t];
    float4 sn = ((const float4*)g_sum)[t];
    int4 cm = ((const int4*)committed)[t];
    int4 lb = ((const int4*)labels)[t];
    int4 cn = ((const int4*)counts)[t];

    float den[4] = {ALPHA + sn.x + GAMMA * (float)cn.x,
                    ALPHA + sn.y + GAMMA * (float)cn.y,
                    ALPHA + sn.z + GAMMA * (float)cn.z,
                    ALPHA + sn.w + GAMMA * (float)cn.w};
    float v[4] = {ch.x / den[0], ch.y / den[1], ch.z / den[2], ch.w / den[3]};
    int cmv[4] = {cm.x, cm.y, cm.z, cm.w};
    int lbv[4] = {lb.x, lb.y, lb.z, lb.w};

    int c0 = t * 4;
    float best = -INFINITY;
    int bidx = c0;
    #pragma unroll
    for (int j = 0; j < 4; j++) {
        if (cmv[j]) {
            atomicAdd(&sbins[wid][lbv[j]], v[j]);
            if (v[j] > best) { best = v[j]; bidx = c0 + j; }  // ascending -> first idx
        }
    }

    // warp argmax, first-index on tie
    #pragma unroll
    for (int o = 16; o > 0; o >>= 1) {
        float ov = __shfl_xor_sync(0xffffffffu, best, o);
        int oi = __shfl_xor_sync(0xffffffffu, bidx, o);
        if (ov > best || (ov == best && oi < bidx)) { best = ov; bidx = oi; }
    }
    if (lane == 0) { wval[wid] = best; widx[wid] = bidx; }
    __syncthreads();

    if (wid == 0) {
        best = (lane < 8) ? wval[lane] : -INFINITY;
        bidx = (lane < 8) ? widx[lane] : (C + 1);
        #pragma unroll
        for (int o = 16; o > 0; o >>= 1) {
            float ov = __shfl_xor_sync(0xffffffffu, best, o);
            int oi = __shfl_xor_sync(0xffffffffu, bidx, o);
            if (ov > best || (ov == best && oi < bidx)) { best = ov; bidx = oi; }
        }
        if (lane == 0) widx[0] = bidx;
    } else if (wid == 1 && lane < NUM_CLASSES) {
        float s = 0.0f;
        #pragma unroll
        for (int w = 0; w < 8; w++) s += sbins[w][lane];
        bins[lane] = s;
    }
    __syncthreads();

    if (t < NUM_CLASSES) {
        int pl = labels[widx[0]];
        out[b * NUM_CLASSES + t] = (t == pl) ? bins[t] : 0.0f;
    }
}

// ---------------------------------------------------------------------------
extern "C" void kernel_launch(void* const* d_in, const int* in_sizes, int n_in,
                              void* d_out, int out_size) {
    const float* x = (const float*)d_in[0];
    const float* T = (const float*)d_in[1];
    const int* committed = (const int*)d_in[2];
    const int* labels = (const int*)d_in[3];
    const int* counts = (const int*)d_in[4];
    float* out = (float*)d_out;

    cudaFuncSetAttribute(k_choice, cudaFuncAttributeMaxDynamicSharedMemorySize,
                         SMEM_BYTES);

    k_prep<<<B, 256>>>(x);
    dim3 g3(C / BN, B / BM, KSPLIT);
    k_choice<<<g3, 1024, SMEM_BYTES>>>(x, T);
    k_final<<<B, 256>>>(committed, labels, counts, out);
}

// round 16
// speedup vs baseline: 1.5393x; 1.5393x over previous
#include <cuda_runtime.h>
#include <math.h>

#define B 128
#define C 1024
#define DIN 1024
#define TWO_D 2048
#define NUM_CLASSES 10
#define ALPHA 1e-3f
#define GAMMA 1e-2f

#define BM 64
#define BN 256
#define KSPLIT 16
#define KSLICE (TWO_D / KSPLIT)   // 128 = BK (whole slice resident in smem)
#define BK KSLICE

#define SA_STRIDE (BM + 4)                // 68 floats
#define SB_STRIDE (BN + 4)                // 260 floats
#define SA_BUF (BK * SA_STRIDE)           // 8704 floats
#define SB_BUF (BK * SB_STRIDE)           // 33280 floats
#define SMEM_BYTES ((SA_BUF + SB_BUF) * 4)  // 167936 B

// Scratch (static device globals; no dynamic allocation)
__device__ float g_pmin[B];
__device__ float g_pmax[B];
__device__ float g_sum[C];         // rowsum(T) via REDG
__device__ float g_choice[B][C];   // numerator via REDG

// ---------------------------------------------------------------------------
// K1 (128 CTAs x 256): row b: zero g_choice row + minmax partial of x row.
// CTA 0 additionally zeroes g_sum.
// ---------------------------------------------------------------------------
__global__ void k_prep(const float* __restrict__ x) {
    int b = blockIdx.x;
    int t = threadIdx.x;  // 256

    ((float4*)&g_choice[b][0])[t] = make_float4(0.f, 0.f, 0.f, 0.f);
    if (b == 0)
        ((float4*)g_sum)[t] = make_float4(0.f, 0.f, 0.f, 0.f);

    float4 v = ((const float4*)(x + (size_t)b * DIN))[t];
    float mn = fminf(fminf(v.x, v.y), fminf(v.z, v.w));
    float mx = fmaxf(fmaxf(v.x, v.y), fmaxf(v.z, v.w));
    #pragma unroll
    for (int o = 16; o > 0; o >>= 1) {
        mn = fminf(mn, __shfl_xor_sync(0xffffffffu, mn, o));
        mx = fmaxf(mx, __shfl_xor_sync(0xffffffffu, mx, o));
    }
    __shared__ float smn[8], smx[8];
    if ((t & 31) == 0) { smn[t >> 5] = mn; smx[t >> 5] = mx; }
    __syncthreads();
    if (t == 0) {
        #pragma unroll
        for (int w = 1; w < 8; w++) { mn = fminf(mn, smn[w]); mx = fmaxf(mx, smx[w]); }
        g_pmin[b] = mn;
        g_pmax[b] = mx;
    }
}

// ---------------------------------------------------------------------------
// K2: min-sum "GEMM". BM=64, BN=256, BK=KSLICE=128, 1024 threads, TM=TN=4.
// grid = (4, 2, 16) = 128 CTAs = one wave.
// Whole K-slice resident in smem: load once, ONE __syncthreads, then an
// uninterrupted 128-step mainloop. A normalized on the fly from x.
// Side-duty: rowsum(T) via per-warp shuffle reduce + 1 REDG per warp-row.
// Epilogue: REDG atomicAdd into g_choice.
// ---------------------------------------------------------------------------
__global__ void __launch_bounds__(1024) k_choice(const float* __restrict__ x,
                                                 const float* __restrict__ T) {
    extern __shared__ float sm[];
    float* sA = sm;              // [BK][SA_STRIDE]
    float* sB = sm + SA_BUF;     // [BK][SB_STRIDE]

    int tid = threadIdx.x;
    int tx = tid & 63;       // n-group -> n0 = tx*4 (BN=256)
    int ty = tid >> 6;       // m-group -> m0 = ty*4 (BM=64)
    int lane = tid & 31;
    int mbase = blockIdx.y * BM;
    int nbase = blockIdx.x * BN;
    int k0 = blockIdx.z * KSLICE;
    bool comp = (k0 >= DIN);
    int xcol = comp ? (k0 - DIN) : k0;
    bool sumDuty = (blockIdx.y == 0);

    // inline global minmax reduce (128 partials -> mnv, sc)
    __shared__ float smn[4], smx[4];
    if (tid < 128) {
        float mn = g_pmin[tid];
        float mx = g_pmax[tid];
        #pragma unroll
        for (int o = 16; o > 0; o >>= 1) {
            mn = fminf(mn, __shfl_xor_sync(0xffffffffu, mn, o));
            mx = fmaxf(mx, __shfl_xor_sync(0xffffffffu, mx, o));
        }
        if ((tid & 31) == 0) { smn[tid >> 5] = mn; smx[tid >> 5] = mx; }
    }
    __syncthreads();
    float mnv = fminf(fminf(smn[0], smn[1]), fminf(smn[2], smn[3]));
    float mxv = fmaxf(fmaxf(smx[0], smx[1]), fmaxf(smx[2], smx[3]));
    float sc = 1.0f / (mxv - mnv + 1e-10f);

    // ---- fill smem: A = 2048 float4 (2/thread), B = 8192 float4 (8/thread)
    // idx -> row = idx>>5, kv = idx&31 (float4 column)
    {
        #pragma unroll
        for (int i = 0; i < 2; i++) {
            int idx = tid + i * 1024;
            int row = idx >> 5;
            int kv = idx & 31;
            float4 v = *(const float4*)&x[(size_t)(mbase + row) * DIN + xcol + kv * 4];
            v.x = (v.x - mnv) * sc; v.y = (v.y - mnv) * sc;
            v.z = (v.z - mnv) * sc; v.w = (v.w - mnv) * sc;
            if (comp) {
                v.x = 1.0f - v.x; v.y = 1.0f - v.y;
                v.z = 1.0f - v.z; v.w = 1.0f - v.w;
            }
            int kc = kv * 4;
            sA[(kc + 0) * SA_STRIDE + row] = v.x;
            sA[(kc + 1) * SA_STRIDE + row] = v.y;
            sA[(kc + 2) * SA_STRIDE + row] = v.z;
            sA[(kc + 3) * SA_STRIDE + row] = v.w;
        }
        #pragma unroll
        for (int i = 0; i < 8; i++) {
            int idx = tid + i * 1024;
            int row = idx >> 5;      // same for all lanes of a warp
            int kv = idx & 31;
            float4 v = *(const float4*)&T[(size_t)(nbase + row) * TWO_D + k0 + kv * 4];
            int kc = kv * 4;
            sB[(kc + 0) * SB_STRIDE + row] = v.x;
            sB[(kc + 1) * SB_STRIDE + row] = v.y;
            sB[(kc + 2) * SB_STRIDE + row] = v.z;
            sB[(kc + 3) * SB_STRIDE + row] = v.w;
            if (sumDuty) {
                float s = (v.x + v.y) + (v.z + v.w);
                #pragma unroll
                for (int o = 16; o > 0; o >>= 1)
                    s += __shfl_xor_sync(0xffffffffu, s, o);
                if (lane == 0)
                    atomicAdd(&g_sum[nbase + row], s);
            }
        }
    }
    __syncthreads();   // the ONLY mainline barrier

    float acc[4][4];
    #pragma unroll
    for (int i = 0; i < 4; i++)
        #pragma unroll
        for (int j = 0; j < 4; j++) acc[i][j] = 0.0f;

    const float* cA = sA + ty * 4;
    const float* cB = sB + tx * 4;
    #pragma unroll 8
    for (int k = 0; k < BK; k++) {
        float4 a = *(const float4*)(cA + k * SA_STRIDE);
        float4 bb = *(const float4*)(cB + k * SB_STRIDE);
        float av[4] = {a.x, a.y, a.z, a.w};
        float bv[4] = {bb.x, bb.y, bb.z, bb.w};
        #pragma unroll
        for (int i = 0; i < 4; i++)
            #pragma unroll
            for (int j = 0; j < 4; j++)
                acc[i][j] += fminf(av[i], bv[j]);
    }

    // fire-and-forget reduction into g_choice (REDG)
    int b0 = mbase + ty * 4;
    int c0 = nbase + tx * 4;
    #pragma unroll
    for (int i = 0; i < 4; i++)
        #pragma unroll
        for (int j = 0; j < 4; j++)
            atomicAdd(&g_choice[b0 + i][c0 + j], acc[i][j]);
}

// ---------------------------------------------------------------------------
// K3: per batch row, 256 threads, 4 categories/thread (float4/int4 loads):
// den = alpha + g_sum[c] + gamma*counts[c]; divide, masked argmax
// (first-index tie), per-label sums via per-warp smem rows, one-hot output.
// committed is int32.
// ---------------------------------------------------------------------------
__global__ void __launch_bounds__(256) k_final(const int* __restrict__ committed,
                                               const int* __restrict__ labels,
                                               const int* __restrict__ counts,
                                               float* __restrict__ out) {
    int b = blockIdx.x;
    int t = threadIdx.x;        // 0..255, cats c = 4t..4t+3
    int lane = t & 31;
    int wid = t >> 5;
    __shared__ float sbins[8][NUM_CLASSES];
    __shared__ float bins[NUM_CLASSES];
    __shared__ float wval[8];
    __shared__ int widx[8];

    if (lane < NUM_CLASSES) sbins[wid][lane] = 0.0f;
    __syncthreads();

    float4 ch = ((const float4*)&g_choice[b][0])[t];
    float4 sn = ((const float4*)g_sum)[t];
    int4 cm = ((const int4*)committed)[t];
    int4 lb = ((const int4*)labels)[t];
    int4 cn = ((const int4*)counts)[t];

    float den[4] = {ALPHA + sn.x + GAMMA * (float)cn.x,
                    ALPHA + sn.y + GAMMA * (float)cn.y,
                    ALPHA + sn.z + GAMMA * (float)cn.z,
                    ALPHA + sn.w + GAMMA * (float)cn.w};
    float v[4] = {ch.x / den[0], ch.y / den[1], ch.z / den[2], ch.w / den[3]};
    int cmv[4] = {cm.x, cm.y, cm.z, cm.w};
    int lbv[4] = {lb.x, lb.y, lb.z, lb.w};

    int c0 = t * 4;
    float best = -INFINITY;
    int bidx = c0;
    #pragma unroll
    for (int j = 0; j < 4; j++) {
        if (cmv[j]) {
            atomicAdd(&sbins[wid][lbv[j]], v[j]);
            if (v[j] > best) { best = v[j]; bidx = c0 + j; }  // ascending -> first idx
        }
    }

    // warp argmax, first-index on tie
    #pragma unroll
    for (int o = 16; o > 0; o >>= 1) {
        float ov = __shfl_xor_sync(0xffffffffu, best, o);
        int oi = __shfl_xor_sync(0xffffffffu, bidx, o);
        if (ov > best || (ov == best && oi < bidx)) { best = ov; bidx = oi; }
    }
    if (lane == 0) { wval[wid] = best; widx[wid] = bidx; }
    __syncthreads();

    if (wid == 0) {
        best = (lane < 8) ? wval[lane] : -INFINITY;
        bidx = (lane < 8) ? widx[lane] : (C + 1);
        #pragma unroll
        for (int o = 16; o > 0; o >>= 1) {
            float ov = __shfl_xor_sync(0xffffffffu, best, o);
            int oi = __shfl_xor_sync(0xffffffffu, bidx, o);
            if (ov > best || (ov == best && oi < bidx)) { best = ov; bidx = oi; }
        }
        if (lane == 0) widx[0] = bidx;
    } else if (wid == 1 && lane < NUM_CLASSES) {
        float s = 0.0f;
        #pragma unroll
        for (int w = 0; w < 8; w++) s += sbins[w][lane];
        bins[lane] = s;
    }
    __syncthreads();

    if (t < NUM_CLASSES) {
        int pl = labels[widx[0]];
        out[b * NUM_CLASSES + t] = (t == pl) ? bins[t] : 0.0f;
    }
}

// ---------------------------------------------------------------------------
extern "C" void kernel_launch(void* const* d_in, const int* in_sizes, int n_in,
                              void* d_out, int out_size) {
    const float* x = (const float*)d_in[0];
    const float* T = (const float*)d_in[1];
    const int* committed = (const int*)d_in[2];
    const int* labels = (const int*)d_in[3];
    const int* counts = (const int*)d_in[4];
    float* out = (float*)d_out;

    cudaFuncSetAttribute(k_choice, cudaFuncAttributeMaxDynamicSharedMemorySize,
                         SMEM_BYTES);

    k_prep<<<B, 256>>>(x);
    dim3 g3(C / BN, B / BM, KSPLIT);
    k_choice<<<g3, 1024, SMEM_BYTES>>>(x, T);
    k_final<<<B, 256>>>(committed, labels, counts, out);
}

// round 17
// speedup vs baseline: 1.7792x; 1.1558x over previous
#include <cuda_runtime.h>
#include <math.h>

#define B 128
#define C 1024
#define DIN 1024
#define TWO_D 2048
#define NUM_CLASSES 10
#define ALPHA 1e-3f
#define GAMMA 1e-2f

#define BM 64
#define BN 256
#define BK 32
#define PAD 4
#define KSPLIT 16
#define KSLICE (TWO_D / KSPLIT)   // 128  (aligned: each slice is in one half)
#define NT (KSLICE / BK)          // 4 tiles

#define SA_STRIDE (BM + PAD)              // 68
#define SB_STRIDE (BN + PAD)              // 260
#define SA_BUF (BK * SA_STRIDE)           // 2176 floats
#define SB_BUF (BK * SB_STRIDE)           // 8320 floats
#define SMEM_FLOATS (2 * SA_BUF + 2 * SB_BUF)
#define SMEM_BYTES (SMEM_FLOATS * 4)      // 83968 B

// Scratch (static device globals; no dynamic allocation).
// INVARIANT: g_choice and g_sum are all-zero at kernel_launch entry —
// zero-initialized at module load, and re-zeroed by k_final / k_prep at the
// end of every call. Deterministic across graph replays.
__device__ float g_pmin[B];
__device__ float g_pmax[B];
__device__ float g_sum[C];         // rowsum(T) via REDG
__device__ float g_choice[B][C];   // numerator via REDG

// ---------------------------------------------------------------------------
// K1 (128 CTAs x 256): minmax partial of x row b. CTA 0 zeroes g_sum
// (g_choice zeroing is deferred to k_final's tail).
// ---------------------------------------------------------------------------
__global__ void k_prep(const float* __restrict__ x) {
    int b = blockIdx.x;
    int t = threadIdx.x;  // 256

    if (b == 0)
        ((float4*)g_sum)[t] = make_float4(0.f, 0.f, 0.f, 0.f);

    float4 v = ((const float4*)(x + (size_t)b * DIN))[t];
    float mn = fminf(fminf(v.x, v.y), fminf(v.z, v.w));
    float mx = fmaxf(fmaxf(v.x, v.y), fmaxf(v.z, v.w));
    #pragma unroll
    for (int o = 16; o > 0; o >>= 1) {
        mn = fminf(mn, __shfl_xor_sync(0xffffffffu, mn, o));
        mx = fmaxf(mx, __shfl_xor_sync(0xffffffffu, mx, o));
    }
    __shared__ float smn[8], smx[8];
    if ((t & 31) == 0) { smn[t >> 5] = mn; smx[t >> 5] = mx; }
    __syncthreads();
    if (t == 0) {
        #pragma unroll
        for (int w = 1; w < 8; w++) { mn = fminf(mn, smn[w]); mx = fmaxf(mx, smx[w]); }
        g_pmin[b] = mn;
        g_pmax[b] = mx;
    }
}

// ---------------------------------------------------------------------------
// K2: min-sum "GEMM". BM=64, BN=256, BK=32, 1024 threads, TM=TN=4.
// grid = (4, 2, 16) = 128 CTAs = one wave, 8 warps/SMSP.
// A built on the fly from x (normalize + optional complement).
// Inline 128->1 minmax reduce at kernel start. Double-buffered dynamic smem.
// Side-product: rowsum(T) partials REDG'd into g_sum (blockIdx.y==0 only).
// Epilogue: REDG atomicAdd into g_choice.
// ---------------------------------------------------------------------------
__global__ void __launch_bounds__(1024) k_choice(const float* __restrict__ x,
                                                 const float* __restrict__ T) {
    extern __shared__ float sm[];
    float* sA = sm;                  // [2][BK][BM+PAD]
    float* sB = sm + 2 * SA_BUF;     // [2][BK][BN+PAD]

    int tid = threadIdx.x;
    int tx = tid & 63;       // n-group -> n0 = tx*4 (BN=256)
    int ty = tid >> 6;       // m-group -> m0 = ty*4 (BM=64)
    int mbase = blockIdx.y * BM;
    int nbase = blockIdx.x * BN;
    int k0 = blockIdx.z * KSLICE;
    bool comp = (k0 >= DIN);
    int xcol = comp ? (k0 - DIN) : k0;
    bool sumDuty = (blockIdx.y == 0);

    // inline global minmax reduce (128 partials -> mnv, sc)
    __shared__ float smn[4], smx[4];
    if (tid < 128) {
        float mn = g_pmin[tid];
        float mx = g_pmax[tid];
        #pragma unroll
        for (int o = 16; o > 0; o >>= 1) {
            mn = fminf(mn, __shfl_xor_sync(0xffffffffu, mn, o));
            mx = fmaxf(mx, __shfl_xor_sync(0xffffffffu, mx, o));
        }
        if ((tid & 31) == 0) { smn[tid >> 5] = mn; smx[tid >> 5] = mx; }
    }
    __syncthreads();
    float mnv = fminf(fminf(smn[0], smn[1]), fminf(smn[2], smn[3]));
    float mxv = fmaxf(fmaxf(smx[0], smx[1]), fmaxf(smx[2], smx[3]));
    float sc = 1.0f / (mxv - mnv + 1e-10f);

    bool hasA = tid < 512;
    int ra = tid >> 3;       // A rows 0..63 (tid<512), B rows 0..127
    int kv = tid & 7;

    const float4* pA  = (const float4*)&x[(size_t)(mbase + (hasA ? ra : 0)) * DIN + xcol + kv * 4];
    const float4* pB0 = (const float4*)&T[(size_t)(nbase + ra) * TWO_D + k0 + kv * 4];
    const float4* pB1 = (const float4*)&T[(size_t)(nbase + ra + 128) * TWO_D + k0 + kv * 4];

    float acc[4][4];
    #pragma unroll
    for (int i = 0; i < 4; i++)
        #pragma unroll
        for (int j = 0; j < 4; j++) acc[i][j] = 0.0f;

    float tsum0 = 0.0f, tsum1 = 0.0f;

    #define XFORM(v) do { \
        v.x = (v.x - mnv) * sc; v.y = (v.y - mnv) * sc; \
        v.z = (v.z - mnv) * sc; v.w = (v.w - mnv) * sc; \
        if (comp) { v.x = 1.0f - v.x; v.y = 1.0f - v.y; \
                    v.z = 1.0f - v.z; v.w = 1.0f - v.w; } \
    } while (0)

    float4 va = make_float4(0.f, 0.f, 0.f, 0.f);
    if (hasA) va = pA[0];
    float4 vb0 = pB0[0], vb1 = pB1[0];
    tsum0 += (vb0.x + vb0.y) + (vb0.z + vb0.w);
    tsum1 += (vb1.x + vb1.y) + (vb1.z + vb1.w);
    {
        int kc = kv * 4;
        if (hasA) {
            XFORM(va);
            float* a = sA + kc * SA_STRIDE;
            a[ra] = va.x; a[SA_STRIDE + ra] = va.y;
            a[2 * SA_STRIDE + ra] = va.z; a[3 * SA_STRIDE + ra] = va.w;
        }
        float* bp = sB + kc * SB_STRIDE;
        bp[ra] = vb0.x; bp[SB_STRIDE + ra] = vb0.y;
        bp[2 * SB_STRIDE + ra] = vb0.z; bp[3 * SB_STRIDE + ra] = vb0.w;
        bp[ra + 128] = vb1.x; bp[SB_STRIDE + ra + 128] = vb1.y;
        bp[2 * SB_STRIDE + ra + 128] = vb1.z; bp[3 * SB_STRIDE + ra + 128] = vb1.w;
    }
    __syncthreads();

    int buf = 0;
    for (int tt = 0; tt < NT; tt++) {
        if (tt + 1 < NT) {   // prefetch next tile (overlaps compute below)
            int o = (tt + 1) * (BK / 4);
            if (hasA) va = pA[o];
            vb0 = pB0[o]; vb1 = pB1[o];
            tsum0 += (vb0.x + vb0.y) + (vb0.z + vb0.w);
            tsum1 += (vb1.x + vb1.y) + (vb1.z + vb1.w);
        }
        const float* cA = sA + buf * SA_BUF + ty * 4;
        const float* cB = sB + buf * SB_BUF + tx * 4;
        #pragma unroll
        for (int k = 0; k < BK; k++) {
            float4 a = *(const float4*)(cA + k * SA_STRIDE);
            float4 bb = *(const float4*)(cB + k * SB_STRIDE);
            float av[4] = {a.x, a.y, a.z, a.w};
            float bv[4] = {bb.x, bb.y, bb.z, bb.w};
            #pragma unroll
            for (int i = 0; i < 4; i++)
                #pragma unroll
                for (int j = 0; j < 4; j++)
                    acc[i][j] += fminf(av[i], bv[j]);
        }
        if (tt + 1 < NT) {
            int nb = buf ^ 1;
            int kc = kv * 4;
            if (hasA) {
                XFORM(va);
                float* a = sA + nb * SA_BUF + kc * SA_STRIDE;
                a[ra] = va.x; a[SA_STRIDE + ra] = va.y;
                a[2 * SA_STRIDE + ra] = va.z; a[3 * SA_STRIDE + ra] = va.w;
            }
            float* bp = sB + nb * SB_BUF + kc * SB_STRIDE;
            bp[ra] = vb0.x; bp[SB_STRIDE + ra] = vb0.y;
            bp[2 * SB_STRIDE + ra] = vb0.z; bp[3 * SB_STRIDE + ra] = vb0.w;
            bp[ra + 128] = vb1.x; bp[SB_STRIDE + ra + 128] = vb1.y;
            bp[2 * SB_STRIDE + ra + 128] = vb1.z; bp[3 * SB_STRIDE + ra + 128] = vb1.w;
            __syncthreads();
            buf = nb;
        }
    }
    #undef XFORM

    if (sumDuty) {
        atomicAdd(&g_sum[nbase + ra], tsum0);
        atomicAdd(&g_sum[nbase + ra + 128], tsum1);
    }

    int b0 = mbase + ty * 4;
    int c0 = nbase + tx * 4;
    #pragma unroll
    for (int i = 0; i < 4; i++)
        #pragma unroll
        for (int j = 0; j < 4; j++)
            atomicAdd(&g_choice[b0 + i][c0 + j], acc[i][j]);
}

// ---------------------------------------------------------------------------
// K3: per batch row, 256 threads, 4 categories/thread (float4/int4 loads):
// den = alpha + g_sum[c] + gamma*counts[c]; divide, masked argmax
// (first-index tie), per-label sums, one-hot output. committed is int32.
// Tail: re-zero this CTA's g_choice row for the next invocation.
// ---------------------------------------------------------------------------
__global__ void __launch_bounds__(256) k_final(const int* __restrict__ committed,
                                               const int* __restrict__ labels,
                                               const int* __restrict__ counts,
                                               float* __restrict__ out) {
    int b = blockIdx.x;
    int t = threadIdx.x;        // 0..255, cats c = 4t..4t+3
    int lane = t & 31;
    int wid = t >> 5;
    __shared__ float sbins[8][NUM_CLASSES];
    __shared__ float bins[NUM_CLASSES];
    __shared__ float wval[8];
    __shared__ int widx[8];

    if (lane < NUM_CLASSES) sbins[wid][lane] = 0.0f;
    __syncthreads();

    float4 ch = ((const float4*)&g_choice[b][0])[t];
    float4 sn = ((const float4*)g_sum)[t];
    int4 cm = ((const int4*)committed)[t];
    int4 lb = ((const int4*)labels)[t];
    int4 cn = ((const int4*)counts)[t];

    // re-zero own g_choice row for the next call (read above already done)
    ((float4*)&g_choice[b][0])[t] = make_float4(0.f, 0.f, 0.f, 0.f);

    float den[4] = {ALPHA + sn.x + GAMMA * (float)cn.x,
                    ALPHA + sn.y + GAMMA * (float)cn.y,
                    ALPHA + sn.z + GAMMA * (float)cn.z,
                    ALPHA + sn.w + GAMMA * (float)cn.w};
    float v[4] = {ch.x / den[0], ch.y / den[1], ch.z / den[2], ch.w / den[3]};
    int cmv[4] = {cm.x, cm.y, cm.z, cm.w};
    int lbv[4] = {lb.x, lb.y, lb.z, lb.w};

    int c0 = t * 4;
    float best = -INFINITY;
    int bidx = c0;
    #pragma unroll
    for (int j = 0; j < 4; j++) {
        if (cmv[j]) {
            atomicAdd(&sbins[wid][lbv[j]], v[j]);
            if (v[j] > best) { best = v[j]; bidx = c0 + j; }  // ascending -> first idx
        }
    }

    // warp argmax, first-index on tie
    #pragma unroll
    for (int o = 16; o > 0; o >>= 1) {
        float ov = __shfl_xor_sync(0xffffffffu, best, o);
        int oi = __shfl_xor_sync(0xffffffffu, bidx, o);
        if (ov > best || (ov == best && oi < bidx)) { best = ov; bidx = oi; }
    }
    if (lane == 0) { wval[wid] = best; widx[wid] = bidx; }
    __syncthreads();

    if (wid == 0) {
        best = (lane < 8) ? wval[lane] : -INFINITY;
        bidx = (lane < 8) ? widx[lane] : (C + 1);
        #pragma unroll
        for (int o = 16; o > 0; o >>= 1) {
            float ov = __shfl_xor_sync(0xffffffffu, best, o);
            int oi = __shfl_xor_sync(0xffffffffu, bidx, o);
            if (ov > best || (ov == best && oi < bidx)) { best = ov; bidx = oi; }
        }
        if (lane == 0) widx[0] = bidx;
    } else if (wid == 1 && lane < NUM_CLASSES) {
        float s = 0.0f;
        #pragma unroll
        for (int w = 0; w < 8; w++) s += sbins[w][lane];
        bins[lane] = s;
    }
    __syncthreads();

    if (t < NUM_CLASSES) {
        int pl = labels[widx[0]];
        out[b * NUM_CLASSES + t] = (t == pl) ? bins[t] : 0.0f;
    }
}

// ---------------------------------------------------------------------------
extern "C" void kernel_launch(void* const* d_in, const int* in_sizes, int n_in,
                              void* d_out, int out_size) {
    const float* x = (const float*)d_in[0];
    const float* T = (const float*)d_in[1];
    const int* committed = (const int*)d_in[2];
    const int* labels = (const int*)d_in[3];
    const int* counts = (const int*)d_in[4];
    float* out = (float*)d_out;

    cudaFuncSetAttribute(k_choice, cudaFuncAttributeMaxDynamicSharedMemorySize,
                         SMEM_BYTES);

    k_prep<<<B, 256>>>(x);
    dim3 g3(C / BN, B / BM, KSPLIT);
    k_choice<<<g3, 1024, SMEM_BYTES>>>(x, T);
    k_final<<<B, 256>>>(committed, labels, counts, out);
}